// round 11
// baseline (speedup 1.0000x reference)
#include <cuda_runtime.h>
#include <cstdint>

#define D 128            // DH == DX == 128

#define CHUNK  8             // nodes per bulk copy (8 * 512B = 4KB)
#define STAGES 2             // per-warp ring depth (8KB/warp)
#define GRID   512           // MUST be <= resident capacity
#define THREADS 128

#define MAX_M 4096
#define MAX_N 262144

// Scratch (no allocations allowed)
__device__ float    g_proj[MAX_M * D];
__device__ int      g_offsets[MAX_M + 1];
__device__ unsigned g_arrive;   // monotonic epoch counter (never reset)

// ---------------------------------------------------------------------------
// PTX helpers
// ---------------------------------------------------------------------------
__device__ __forceinline__ uint32_t smem_u32(const void* p) {
    return (uint32_t)__cvta_generic_to_shared(p);
}
__device__ __forceinline__ void mbar_init(uint32_t bar, uint32_t cnt) {
    asm volatile("mbarrier.init.shared.b64 [%0], %1;" :: "r"(bar), "r"(cnt) : "memory");
}
__device__ __forceinline__ void mbar_expect(uint32_t bar, uint32_t bytes) {
    asm volatile("mbarrier.arrive.expect_tx.shared.b64 _, [%0], %1;"
                 :: "r"(bar), "r"(bytes) : "memory");
}
__device__ __forceinline__ void bulk_ld(uint32_t dst, const void* src,
                                        uint32_t bytes, uint32_t bar) {
    asm volatile(
        "cp.async.bulk.shared::cta.global.mbarrier::complete_tx::bytes [%0], [%1], %2, [%3];"
        :: "r"(dst), "l"(src), "r"(bytes), "r"(bar) : "memory");
}
__device__ __forceinline__ void mbar_wait(uint32_t bar, uint32_t phase) {
    uint32_t done;
    asm volatile(
        "{\n\t.reg .pred p;\n\t"
        "mbarrier.try_wait.parity.acquire.cta.shared::cta.b64 p, [%1], %2;\n\t"
        "selp.b32 %0, 1, 0, p;\n\t}"
        : "=r"(done) : "r"(bar), "r"(phase) : "memory");
    if (!done) {
        asm volatile(
            "{\n\t.reg .pred P1;\n\t"
            "WAIT_LOOP_%=:\n\t"
            "mbarrier.try_wait.parity.acquire.cta.shared::cta.b64 P1, [%0], %1, 0x989680;\n\t"
            "@P1 bra.uni WAIT_DONE_%=;\n\t"
            "bra.uni WAIT_LOOP_%=;\n\t"
            "WAIT_DONE_%=:\n\t}"
            :: "r"(bar), "r"(phase) : "memory");
    }
}
__device__ __forceinline__ void pair_bar(int pp) {
    asm volatile("bar.sync %0, 64;" :: "r"(1 + pp) : "memory");
}

// ---------------------------------------------------------------------------
// Flash helpers
// ---------------------------------------------------------------------------
__device__ __forceinline__ float warp_dot(float4 v, float4 p) {
    float d = fmaf(v.x, p.x, fmaf(v.y, p.y, fmaf(v.z, p.z, v.w * p.w)));
    d += __shfl_xor_sync(0xffffffffu, d, 16);
    d += __shfl_xor_sync(0xffffffffu, d, 8);
    d += __shfl_xor_sync(0xffffffffu, d, 4);
    d += __shfl_xor_sync(0xffffffffu, d, 2);
    d += __shfl_xor_sync(0xffffffffu, d, 1);
    return d;
}

__device__ __forceinline__ void flash4(const float4* __restrict__ b, float4 p,
                                       float& m_w, float& z_w, float4& acc) {
    float4 v0 = b[0];
    float4 v1 = b[32];
    float4 v2 = b[64];
    float4 v3 = b[96];
    float d0 = warp_dot(v0, p);
    float d1 = warp_dot(v1, p);
    float d2 = warp_dot(v2, p);
    float d3 = warp_dot(v3, p);
    float m_new = fmaxf(fmaxf(m_w, fmaxf(d0, d1)), fmaxf(d2, d3));
    float c  = __expf(m_w - m_new);
    float e0 = __expf(d0 - m_new);
    float e1 = __expf(d1 - m_new);
    float e2 = __expf(d2 - m_new);
    float e3 = __expf(d3 - m_new);
    z_w   = fmaf(z_w, c, (e0 + e1) + (e2 + e3));
    acc.x = fmaf(acc.x, c, fmaf(e0, v0.x, fmaf(e1, v1.x, fmaf(e2, v2.x, e3 * v3.x))));
    acc.y = fmaf(acc.y, c, fmaf(e0, v0.y, fmaf(e1, v1.y, fmaf(e2, v2.y, e3 * v3.y))));
    acc.z = fmaf(acc.z, c, fmaf(e0, v0.z, fmaf(e1, v1.z, fmaf(e2, v2.z, e3 * v3.z))));
    acc.w = fmaf(acc.w, c, fmaf(e0, v0.w, fmaf(e1, v1.w, fmaf(e2, v2.w, e3 * v3.w))));
    m_w = m_new;
}

__device__ __forceinline__ void flash1(float4 v, float4 p,
                                       float& m_w, float& z_w, float4& acc) {
    float d  = warp_dot(v, p);
    float m_new = fmaxf(m_w, d);
    float c = __expf(m_w - m_new);
    float e = __expf(d - m_new);
    z_w   = fmaf(z_w, c, e);
    acc.x = fmaf(acc.x, c, e * v.x);
    acc.y = fmaf(acc.y, c, e * v.y);
    acc.z = fmaf(acc.z, c, e * v.z);
    acc.w = fmaf(acc.w, c, e * v.w);
    m_w = m_new;
}

// ---------------------------------------------------------------------------
// FUSED kernel: phase 1 (offsets + proj) -> device barrier ->
// phase 2 = R5-style TWO-WARPS-PER-GRAPH attn, persistent over graph pairs,
// pair-local combine via named barriers (no cross-pair coupling).
// ---------------------------------------------------------------------------
__global__ __launch_bounds__(THREADS, 4)
void fused_kernel(const float* __restrict__ h,
                  const float* __restrict__ a,
                  const float* __restrict__ x,
                  const int*   __restrict__ seg,
                  float* __restrict__ out,
                  int n, int m) {
    extern __shared__ unsigned char dyn[];   // 36KB: phase1 overlay / phase2 ring
    __shared__ uint64_t s_bar[4][STAGES];
    __shared__ float    s_m[4];
    __shared__ float    s_z[4];
    __shared__ float4   s_accs[2][32];

    int tid  = threadIdx.x;
    int lane = tid & 31;
    int w    = tid >> 5;    // 0..3
    int pp   = w >> 1;      // pair 0..1
    int half = w & 1;

    // ======================= PHASE 1a: segment offsets ======================
    {
        int nt4 = (n + 3) >> 2;
        for (int t = blockIdx.x * THREADS + tid; t < nt4;
             t += gridDim.x * THREADS) {
            int base = t * 4;
            int4 v = ((const int4*)seg)[t];
            int prev = (base == 0) ? -1 : __ldg(&seg[base - 1]);
            int ids[4] = {v.x, v.y, v.z, v.w};
#pragma unroll
            for (int k = 0; k < 4; k++) {
                int s = ids[k];
                for (int g = prev + 1; g <= s; ++g) g_offsets[g] = base + k;
                prev = s;
            }
            if (base + 4 >= n) {
                for (int g = prev + 1; g <= m; ++g) g_offsets[g] = n;
            }
        }
    }

    // ======================= PHASE 1b: proj = h @ a =========================
    {
        float* a_sh = (float*)dyn;                 // 32KB: one k-half of a
        float* h_sh = (float*)(dyn + 32768);       // 4KB:  8 h rows

        int cg = lane;
        int rg = w;

        const float4* h4 = (const float4*)h;
        const float4* a4 = (const float4*)a;
        float4* hsh4 = (float4*)h_sh;
        float4* ash4 = (float4*)a_sh;

        for (int rb = blockIdx.x * 8; rb < m; rb += gridDim.x * 8) {
            for (int i = tid; i < 8 * 32; i += THREADS) {
                int gi = rb * 32 + i;
                if (gi < m * 32) hsh4[i] = h4[gi];
            }

            float acc[2][4];
#pragma unroll
            for (int r = 0; r < 2; r++)
                acc[r][0] = acc[r][1] = acc[r][2] = acc[r][3] = 0.f;

            for (int hv2 = 0; hv2 < 2; hv2++) {
                __syncthreads();
                for (int i = tid; i < 64 * 32; i += THREADS)
                    ash4[i] = a4[hv2 * 64 * 32 + i];
                __syncthreads();

#pragma unroll 8
                for (int k2 = 0; k2 < 64; k2++) {
                    float4 av = ash4[k2 * 32 + cg];
                    int k = hv2 * 64 + k2;
#pragma unroll
                    for (int r = 0; r < 2; r++) {
                        float hv = h_sh[(rg * 2 + r) * D + k];
                        acc[r][0] = fmaf(hv, av.x, acc[r][0]);
                        acc[r][1] = fmaf(hv, av.y, acc[r][1]);
                        acc[r][2] = fmaf(hv, av.z, acc[r][2]);
                        acc[r][3] = fmaf(hv, av.w, acc[r][3]);
                    }
                }
            }

            float4* p4 = (float4*)g_proj;
#pragma unroll
            for (int r = 0; r < 2; r++) {
                int row = rb + rg * 2 + r;
                if (row < m)
                    p4[row * 32 + cg] =
                        make_float4(acc[r][0], acc[r][1], acc[r][2], acc[r][3]);
            }
            __syncthreads();
        }
    }

    // ======================= DEVICE-WIDE BARRIER ============================
    __syncthreads();
    if (tid == 0) {
        __threadfence();
        unsigned t0 = atomicAdd(&g_arrive, 1u);
        unsigned target = (t0 / gridDim.x + 1u) * gridDim.x;
        while (atomicAdd(&g_arrive, 0u) < target) __nanosleep(128);
        __threadfence();
    }
    __syncthreads();

    // ======================= PHASE 2: two-warps-per-graph attn ==============
    float4* buf = (float4*)dyn + w * STAGES * (CHUNK * 32);   // 8KB per warp

    if (lane == 0)
        for (int s = 0; s < STAGES; s++) mbar_init(smem_u32(&s_bar[w][s]), 1);
    __syncthreads();

    const float4* x4   = (const float4*)x;
    const float4* pr4  = (const float4*)g_proj;
    float4*       out4 = (float4*)out;
    const float NEG_INF = -3.402823466e38f;

    unsigned cc = 0;   // per-warp global chunk counter: ring stage + parity

    for (int pb = blockIdx.x; pb * 2 < m; pb += gridDim.x) {
        int g = pb * 2 + pp;
        bool active = (g < m);
        int s0 = 0, e0 = 0;
        if (active) { s0 = g_offsets[g]; e0 = g_offsets[g + 1]; }
        int cnt = e0 - s0;
        int h0  = (cnt + 1) >> 1;
        int beg = half ? (s0 + h0) : s0;
        int fin = half ? e0 : (s0 + h0);
        int len = fin - beg;
        int nfull = (len > 0) ? (len >> 3) : 0;

        float4 p = make_float4(0.f, 0.f, 0.f, 0.f);
        if (active && cnt > 0)
            p = pr4[g * 32 + lane];

        // ---- prologue: fill the pipeline ----
        if (lane == 0) {
            int npre = nfull < STAGES ? nfull : STAGES;
            for (int k = 0; k < npre; k++) {
                int st = (cc + k) & 1;
                uint32_t b = smem_u32(&s_bar[w][st]);
                mbar_expect(b, CHUNK * 512u);
                bulk_ld(smem_u32(buf + st * (CHUNK * 32)),
                        x4 + (size_t)(beg + k * CHUNK) * 32, CHUNK * 512u, b);
            }
        }

        float  m_w = NEG_INF;
        float  z_w = 0.f;
        float4 acc = make_float4(0.f, 0.f, 0.f, 0.f);

        // ---- main pipelined loop ----
        for (int c = 0; c < nfull; c++) {
            unsigned q = cc + c;
            int st = q & 1;
            mbar_wait(smem_u32(&s_bar[w][st]), (q >> 1) & 1);
            const float4* b = buf + st * (CHUNK * 32) + lane;
            flash4(b,       p, m_w, z_w, acc);   // nodes 0..3
            flash4(b + 128, p, m_w, z_w, acc);   // nodes 4..7
            if (c + STAGES < nfull && lane == 0) {
                uint32_t bb = smem_u32(&s_bar[w][st]);
                mbar_expect(bb, CHUNK * 512u);
                bulk_ld(smem_u32(buf + st * (CHUNK * 32)),
                        x4 + (size_t)(beg + (c + STAGES) * CHUNK) * 32,
                        CHUNK * 512u, bb);
            }
        }
        cc += nfull;

        // ---- remainder nodes (<CHUNK) via direct LDG ----
        for (int i = beg + nfull * CHUNK; i < fin; ++i)
            flash1(x4[(size_t)i * 32 + lane], p, m_w, z_w, acc);

        // ---- pair combine (named barrier: pairs don't couple) ----
        if (lane == 0) { s_m[w] = m_w; s_z[w] = z_w; }
        if (half) s_accs[pp][lane] = acc;
        pair_bar(pp);

        if (!half && active) {
            if (cnt <= 0) {
                out4[g * 32 + lane] = make_float4(0.f, 0.f, 0.f, 0.f);
            } else {
                float  m1 = s_m[w + 1];
                float  z1 = s_z[w + 1];
                float4 a1 = s_accs[pp][lane];
                float mg = fmaxf(m_w, m1);       // finite: half0 non-empty
                float f0 = __expf(m_w - mg);
                float f1 = __expf(m1 - mg);      // 0 if half1 empty
                float z  = fmaf(z_w, f0, z1 * f1);
                float inv = 1.f / z;
                out4[g * 32 + lane] = make_float4(
                    fmaf(acc.x, f0, a1.x * f1) * inv,
                    fmaf(acc.y, f0, a1.y * f1) * inv,
                    fmaf(acc.z, f0, a1.z * f1) * inv,
                    fmaf(acc.w, f0, a1.w * f1) * inv);
            }
        }
        pair_bar(pp);   // protect s_m/s_z/s_accs before next iteration
    }
}

// ---------------------------------------------------------------------------
// Launch: inputs per metadata order: h (M*128 f32), x (N*128 f32),
// a (128*128 f32), segment_ids (N int32). Output: M*128 f32.
// ---------------------------------------------------------------------------
extern "C" void kernel_launch(void* const* d_in, const int* in_sizes, int n_in,
                              void* d_out, int out_size) {
    const float* h   = (const float*)d_in[0];
    const float* x   = (const float*)d_in[1];
    const float* a   = (const float*)d_in[2];
    const int*   seg = (const int*)d_in[3];
    float* out = (float*)d_out;

    int m = in_sizes[0] / D;   // 4096
    int n = in_sizes[3];       // 262144

    int smem_bytes = 36864;    // max(phase1 overlay 36KB, phase2 ring 32KB)
    static bool attr_set = false;
    if (!attr_set) {
        cudaFuncSetAttribute(fused_kernel,
                             cudaFuncAttributeMaxDynamicSharedMemorySize,
                             smem_bytes);
        attr_set = true;
    }
    fused_kernel<<<GRID, THREADS, smem_bytes>>>(h, a, x, seg, out, n, m);
}

// round 12
// speedup vs baseline: 1.1380x; 1.1380x over previous
#include <cuda_runtime.h>
#include <cstdint>

#define D 128            // DH == DX == 128
#define MAX_M 4096
#define MAX_N 262144

#define PROJ_BLOCKS 64       // 64 rows each -> 4096 rows (fat blocks)
#define CHUNK  8             // nodes per bulk copy (8 * 512B = 4KB)
#define STAGES 2

// Scratch (no allocations allowed): proj matrix + segment offsets
__device__ float g_proj[MAX_M * D];
__device__ int   g_offsets[MAX_M + 1];

// ---------------------------------------------------------------------------
// PTX helpers: mbarrier + cp.async.bulk
// ---------------------------------------------------------------------------
__device__ __forceinline__ uint32_t smem_u32(const void* p) {
    return (uint32_t)__cvta_generic_to_shared(p);
}
__device__ __forceinline__ void mbar_init(uint32_t bar, uint32_t cnt) {
    asm volatile("mbarrier.init.shared.b64 [%0], %1;" :: "r"(bar), "r"(cnt) : "memory");
}
__device__ __forceinline__ void mbar_expect(uint32_t bar, uint32_t bytes) {
    asm volatile("mbarrier.arrive.expect_tx.shared.b64 _, [%0], %1;"
                 :: "r"(bar), "r"(bytes) : "memory");
}
__device__ __forceinline__ void bulk_ld(uint32_t dst, const void* src,
                                        uint32_t bytes, uint32_t bar) {
    asm volatile(
        "cp.async.bulk.shared::cta.global.mbarrier::complete_tx::bytes [%0], [%1], %2, [%3];"
        :: "r"(dst), "l"(src), "r"(bytes), "r"(bar) : "memory");
}
__device__ __forceinline__ void mbar_wait(uint32_t bar, uint32_t phase) {
    uint32_t done;
    asm volatile(
        "{\n\t.reg .pred p;\n\t"
        "mbarrier.try_wait.parity.acquire.cta.shared::cta.b64 p, [%1], %2;\n\t"
        "selp.b32 %0, 1, 0, p;\n\t}"
        : "=r"(done) : "r"(bar), "r"(phase) : "memory");
    if (!done) {
        asm volatile(
            "{\n\t.reg .pred P1;\n\t"
            "WAIT_LOOP_%=:\n\t"
            "mbarrier.try_wait.parity.acquire.cta.shared::cta.b64 P1, [%0], %1, 0x989680;\n\t"
            "@P1 bra.uni WAIT_DONE_%=;\n\t"
            "bra.uni WAIT_LOOP_%=;\n\t"
            "WAIT_DONE_%=:\n\t}"
            :: "r"(bar), "r"(phase) : "memory");
    }
}

// ---------------------------------------------------------------------------
// Kernel A (fused): blocks [0, PROJ_BLOCKS): proj = h @ a, FAT-BLOCK design.
// 64 blocks x 256 thr, 64 rows/block. Warp rg owns rows rg*8..rg*8+7; lane cg
// owns cols cg*4..cg*4+3 (8x4 register tile). `a` staged ONCE in 64KB smem,
// h tile 32KB; h read as warp-uniform float4 (broadcast, 1 crossbar phase).
// `a` smem traffic = 64 blocks x 512KB = 32MB (4x less than thin-block
// variants) -> crossbar no longer binds; FFMA issue (~2us) does.
// Blocks [PROJ_BLOCKS, ...): segment offsets from sorted segment_ids.
// ---------------------------------------------------------------------------
__global__ __launch_bounds__(256) void pre_kernel(const float* __restrict__ h,
                                                  const float* __restrict__ a,
                                                  const int* __restrict__ seg,
                                                  int n, int m) {
    extern __shared__ unsigned char dyn[];
    int tid = threadIdx.x;

    if (blockIdx.x < PROJ_BLOCKS) {
        float4* a_sh4 = (float4*)dyn;              // 64 KB: all of a
        float4* h_sh4 = (float4*)(dyn + 65536);    // 32 KB: 64 h rows

        int cg = tid & 31;    // cols cg*4..cg*4+3
        int rg = tid >> 5;    // rows rg*8..rg*8+7
        int rowBase = blockIdx.x * 64;

        const float4* h4 = (const float4*)h;
        const float4* a4 = (const float4*)a;

        // stage a (4096 float4) and h tile (2048 float4)
#pragma unroll
        for (int i = 0; i < 16; i++)
            a_sh4[tid + i * 256] = a4[tid + i * 256];
#pragma unroll
        for (int i = 0; i < 8; i++)
            h_sh4[tid + i * 256] = h4[rowBase * 32 + tid + i * 256];
        __syncthreads();

        float acc[8][4];
#pragma unroll
        for (int r = 0; r < 8; r++)
#pragma unroll
            for (int c = 0; c < 4; c++) acc[r][c] = 0.f;

#pragma unroll 2
        for (int k4 = 0; k4 < 32; k4++) {
            float4 av0 = a_sh4[(k4 * 4 + 0) * 32 + cg];
            float4 av1 = a_sh4[(k4 * 4 + 1) * 32 + cg];
            float4 av2 = a_sh4[(k4 * 4 + 2) * 32 + cg];
            float4 av3 = a_sh4[(k4 * 4 + 3) * 32 + cg];
#pragma unroll
            for (int r = 0; r < 8; r++) {
                float4 hq = h_sh4[(rg * 8 + r) * 32 + k4];  // warp-uniform
                acc[r][0] = fmaf(hq.x, av0.x, fmaf(hq.y, av1.x,
                            fmaf(hq.z, av2.x, fmaf(hq.w, av3.x, acc[r][0]))));
                acc[r][1] = fmaf(hq.x, av0.y, fmaf(hq.y, av1.y,
                            fmaf(hq.z, av2.y, fmaf(hq.w, av3.y, acc[r][1]))));
                acc[r][2] = fmaf(hq.x, av0.z, fmaf(hq.y, av1.z,
                            fmaf(hq.z, av2.z, fmaf(hq.w, av3.z, acc[r][2]))));
                acc[r][3] = fmaf(hq.x, av0.w, fmaf(hq.y, av1.w,
                            fmaf(hq.z, av2.w, fmaf(hq.w, av3.w, acc[r][3]))));
            }
        }

        float4* p4 = (float4*)g_proj;
#pragma unroll
        for (int r = 0; r < 8; r++) {
            int row = rowBase + rg * 8 + r;
            p4[row * 32 + cg] =
                make_float4(acc[r][0], acc[r][1], acc[r][2], acc[r][3]);
        }
    } else {
        // ---------------- segment offsets (int4 per thread) ----------------
        int t = (blockIdx.x - PROJ_BLOCKS) * 256 + tid;   // ids [4t, 4t+4)
        int base = t * 4;
        if (base >= n) return;
        int4 v = ((const int4*)seg)[t];
        int prev = (base == 0) ? -1 : __ldg(&seg[base - 1]);

        int ids[4] = {v.x, v.y, v.z, v.w};
#pragma unroll
        for (int k = 0; k < 4; k++) {
            int s = ids[k];
            for (int g = prev + 1; g <= s; ++g) g_offsets[g] = base + k;
            prev = s;
        }
        if (base + 4 >= n) {
            for (int g = prev + 1; g <= m; ++g) g_offsets[g] = n;
        }
    }
}

// ---------------------------------------------------------------------------
// Flash helpers
// ---------------------------------------------------------------------------
__device__ __forceinline__ float warp_dot(float4 v, float4 p) {
    float d = fmaf(v.x, p.x, fmaf(v.y, p.y, fmaf(v.z, p.z, v.w * p.w)));
    d += __shfl_xor_sync(0xffffffffu, d, 16);
    d += __shfl_xor_sync(0xffffffffu, d, 8);
    d += __shfl_xor_sync(0xffffffffu, d, 4);
    d += __shfl_xor_sync(0xffffffffu, d, 2);
    d += __shfl_xor_sync(0xffffffffu, d, 1);
    return d;
}

__device__ __forceinline__ void flash4(const float4* __restrict__ b, float4 p,
                                       float& m_w, float& z_w, float4& acc) {
    float4 v0 = b[0];
    float4 v1 = b[32];
    float4 v2 = b[64];
    float4 v3 = b[96];
    float d0 = warp_dot(v0, p);
    float d1 = warp_dot(v1, p);
    float d2 = warp_dot(v2, p);
    float d3 = warp_dot(v3, p);
    float m_new = fmaxf(fmaxf(m_w, fmaxf(d0, d1)), fmaxf(d2, d3));
    float c  = __expf(m_w - m_new);
    float e0 = __expf(d0 - m_new);
    float e1 = __expf(d1 - m_new);
    float e2 = __expf(d2 - m_new);
    float e3 = __expf(d3 - m_new);
    z_w   = fmaf(z_w, c, (e0 + e1) + (e2 + e3));
    acc.x = fmaf(acc.x, c, fmaf(e0, v0.x, fmaf(e1, v1.x, fmaf(e2, v2.x, e3 * v3.x))));
    acc.y = fmaf(acc.y, c, fmaf(e0, v0.y, fmaf(e1, v1.y, fmaf(e2, v2.y, e3 * v3.y))));
    acc.z = fmaf(acc.z, c, fmaf(e0, v0.z, fmaf(e1, v1.z, fmaf(e2, v2.z, e3 * v3.z))));
    acc.w = fmaf(acc.w, c, fmaf(e0, v0.w, fmaf(e1, v1.w, fmaf(e2, v2.w, e3 * v3.w))));
    m_w = m_new;
}

__device__ __forceinline__ void flash1(float4 v, float4 p,
                                       float& m_w, float& z_w, float4& acc) {
    float d  = warp_dot(v, p);
    float m_new = fmaxf(m_w, d);
    float c = __expf(m_w - m_new);
    float e = __expf(d - m_new);
    z_w   = fmaf(z_w, c, e);
    acc.x = fmaf(acc.x, c, e * v.x);
    acc.y = fmaf(acc.y, c, e * v.y);
    acc.z = fmaf(acc.z, c, e * v.z);
    acc.w = fmaf(acc.w, c, e * v.w);
    m_w = m_new;
}

// ---------------------------------------------------------------------------
// Kernel B: TWO WARPS PER GRAPH, bulk-async pipelined online softmax.
// (Round-5 version verbatim — best measured attn at 30.7us.)
// ---------------------------------------------------------------------------
__global__ __launch_bounds__(128) void attn_kernel(const float* __restrict__ x,
                                                   float* __restrict__ out,
                                                   int m) {
    __shared__ float4   s_buf[4][STAGES][CHUNK * 32];  // 32 KB
    __shared__ uint64_t s_bar[4][STAGES];
    __shared__ float    s_m[4];
    __shared__ float    s_z[4];
    __shared__ float4   s_accs[2][32];

    int tid  = threadIdx.x;
    int lane = tid & 31;
    int w    = tid >> 5;    // 0..3
    int pp   = w >> 1;      // pair 0..1
    int half = w & 1;
    int g    = blockIdx.x * 2 + pp;

    if (lane == 0) {
        mbar_init(smem_u32(&s_bar[w][0]), 1);
        mbar_init(smem_u32(&s_bar[w][1]), 1);
    }
    __syncthreads();

    bool active = (g < m);
    int s0 = 0, e0 = 0;
    if (active) { s0 = g_offsets[g]; e0 = g_offsets[g + 1]; }
    int cnt = e0 - s0;
    int h0  = (cnt + 1) >> 1;
    int beg = half ? (s0 + h0) : s0;
    int fin = half ? e0 : (s0 + h0);
    int len = fin - beg;
    int nfull = len >> 3;            // full CHUNK-node chunks

    const float4* x4 = (const float4*)x;

    float4 p = make_float4(0.f, 0.f, 0.f, 0.f);
    if (active && cnt > 0)
        p = ((const float4*)g_proj)[g * 32 + lane];

    // ---- prologue: fill the pipeline ----
    if (lane == 0) {
        int npre = nfull < STAGES ? nfull : STAGES;
        for (int k = 0; k < npre; k++) {
            uint32_t bar = smem_u32(&s_bar[w][k]);
            mbar_expect(bar, CHUNK * 512u);
            bulk_ld(smem_u32(&s_buf[w][k][0]),
                    x4 + (size_t)(beg + k * CHUNK) * 32, CHUNK * 512u, bar);
        }
    }

    const float NEG_INF = -3.402823466e38f;
    float  m_w = NEG_INF;
    float  z_w = 0.f;
    float4 acc = make_float4(0.f, 0.f, 0.f, 0.f);

    // ---- main pipelined loop ----
    for (int c = 0; c < nfull; c++) {
        int st = c & 1;
        mbar_wait(smem_u32(&s_bar[w][st]), (c >> 1) & 1);
        const float4* b = &s_buf[w][st][lane];
        flash4(b,       p, m_w, z_w, acc);   // nodes 0..3
        flash4(b + 128, p, m_w, z_w, acc);   // nodes 4..7
        if (c + 2 < nfull && lane == 0) {
            uint32_t bar = smem_u32(&s_bar[w][st]);
            mbar_expect(bar, CHUNK * 512u);
            bulk_ld(smem_u32(&s_buf[w][st][0]),
                    x4 + (size_t)(beg + (c + 2) * CHUNK) * 32, CHUNK * 512u, bar);
        }
    }

    // ---- remainder nodes (<CHUNK) via direct LDG ----
    for (int i = beg + nfull * CHUNK; i < fin; ++i)
        flash1(x4[(size_t)i * 32 + lane], p, m_w, z_w, acc);

    // ---- pair combine ----
    if (lane == 0) { s_m[w] = m_w; s_z[w] = z_w; }
    if (half) s_accs[pp][lane] = acc;
    __syncthreads();

    if (!half && active) {
        float4* out4 = (float4*)out;
        if (cnt <= 0) {
            out4[g * 32 + lane] = make_float4(0.f, 0.f, 0.f, 0.f);
        } else {
            float  m1 = s_m[w + 1];
            float  z1 = s_z[w + 1];
            float4 a1 = s_accs[pp][lane];
            float mg = fmaxf(m_w, m1);       // finite: half0 non-empty
            float f0 = __expf(m_w - mg);
            float f1 = __expf(m1 - mg);      // 0 if half1 empty
            float z  = fmaf(z_w, f0, z1 * f1);
            float inv = 1.f / z;
            out4[g * 32 + lane] = make_float4(
                fmaf(acc.x, f0, a1.x * f1) * inv,
                fmaf(acc.y, f0, a1.y * f1) * inv,
                fmaf(acc.z, f0, a1.z * f1) * inv,
                fmaf(acc.w, f0, a1.w * f1) * inv);
        }
    }
}

// ---------------------------------------------------------------------------
// Launch: inputs per metadata order: h (M*128 f32), x (N*128 f32),
// a (128*128 f32), segment_ids (N int32). Output: M*128 f32.
// ---------------------------------------------------------------------------
extern "C" void kernel_launch(void* const* d_in, const int* in_sizes, int n_in,
                              void* d_out, int out_size) {
    const float* h   = (const float*)d_in[0];
    const float* x   = (const float*)d_in[1];
    const float* a   = (const float*)d_in[2];
    const int*   seg = (const int*)d_in[3];
    float* out = (float*)d_out;

    int m = in_sizes[0] / D;   // 4096
    int n = in_sizes[3];       // 262144

    int pre_smem = 65536 + 32768;   // a (64KB) + h tile (32KB)
    static bool attr_set = false;
    if (!attr_set) {
        cudaFuncSetAttribute(pre_kernel,
                             cudaFuncAttributeMaxDynamicSharedMemorySize,
                             pre_smem);
        attr_set = true;
    }

    int n4 = (n + 3) / 4;
    int off_blocks = (n4 + 255) / 256;
    pre_kernel<<<PROJ_BLOCKS + off_blocks, 256, pre_smem>>>(h, a, seg, n, m);
    attn_kernel<<<(m + 1) / 2, 128>>>(x, out, m);
}

// round 14
// speedup vs baseline: 1.1451x; 1.0062x over previous
#include <cuda_runtime.h>
#include <cstdint>

#define D 128            // DH == DX == 128
#define MAX_M 4096
#define MAX_N 262144

#define PROJ_BLOCKS 64       // 64 rows each -> 4096 rows (fat blocks)
#define CHUNK  8             // nodes per bulk copy (8 * 512B = 4KB)
#define STAGES 2

// Scratch (no allocations allowed): proj matrix + segment offsets
__device__ float g_proj[MAX_M * D];
__device__ int   g_offsets[MAX_M + 1];

// ---------------------------------------------------------------------------
// PTX helpers: mbarrier + cp.async.bulk
// ---------------------------------------------------------------------------
__device__ __forceinline__ uint32_t smem_u32(const void* p) {
    return (uint32_t)__cvta_generic_to_shared(p);
}
__device__ __forceinline__ void mbar_init(uint32_t bar, uint32_t cnt) {
    asm volatile("mbarrier.init.shared.b64 [%0], %1;" :: "r"(bar), "r"(cnt) : "memory");
}
__device__ __forceinline__ void mbar_expect(uint32_t bar, uint32_t bytes) {
    asm volatile("mbarrier.arrive.expect_tx.shared.b64 _, [%0], %1;"
                 :: "r"(bar), "r"(bytes) : "memory");
}
__device__ __forceinline__ void bulk_ld(uint32_t dst, const void* src,
                                        uint32_t bytes, uint32_t bar) {
    asm volatile(
        "cp.async.bulk.shared::cta.global.mbarrier::complete_tx::bytes [%0], [%1], %2, [%3];"
        :: "r"(dst), "l"(src), "r"(bytes), "r"(bar) : "memory");
}
__device__ __forceinline__ void mbar_wait(uint32_t bar, uint32_t phase) {
    uint32_t done;
    asm volatile(
        "{\n\t.reg .pred p;\n\t"
        "mbarrier.try_wait.parity.acquire.cta.shared::cta.b64 p, [%1], %2;\n\t"
        "selp.b32 %0, 1, 0, p;\n\t}"
        : "=r"(done) : "r"(bar), "r"(phase) : "memory");
    if (!done) {
        asm volatile(
            "{\n\t.reg .pred P1;\n\t"
            "WAIT_LOOP_%=:\n\t"
            "mbarrier.try_wait.parity.acquire.cta.shared::cta.b64 P1, [%0], %1, 0x989680;\n\t"
            "@P1 bra.uni WAIT_DONE_%=;\n\t"
            "bra.uni WAIT_LOOP_%=;\n\t"
            "WAIT_DONE_%=:\n\t}"
            :: "r"(bar), "r"(phase) : "memory");
    }
}

// ---------------------------------------------------------------------------
// Kernel A (fused, R12 version verbatim — proven win): proj + offsets
// ---------------------------------------------------------------------------
__global__ __launch_bounds__(256) void pre_kernel(const float* __restrict__ h,
                                                  const float* __restrict__ a,
                                                  const int* __restrict__ seg,
                                                  int n, int m) {
    extern __shared__ unsigned char dyn[];
    int tid = threadIdx.x;

    if (blockIdx.x < PROJ_BLOCKS) {
        float4* a_sh4 = (float4*)dyn;              // 64 KB: all of a
        float4* h_sh4 = (float4*)(dyn + 65536);    // 32 KB: 64 h rows

        int cg = tid & 31;
        int rg = tid >> 5;
        int rowBase = blockIdx.x * 64;

        const float4* h4 = (const float4*)h;
        const float4* a4 = (const float4*)a;

#pragma unroll
        for (int i = 0; i < 16; i++)
            a_sh4[tid + i * 256] = a4[tid + i * 256];
#pragma unroll
        for (int i = 0; i < 8; i++)
            h_sh4[tid + i * 256] = h4[rowBase * 32 + tid + i * 256];
        __syncthreads();

        float acc[8][4];
#pragma unroll
        for (int r = 0; r < 8; r++)
#pragma unroll
            for (int c = 0; c < 4; c++) acc[r][c] = 0.f;

#pragma unroll 2
        for (int k4 = 0; k4 < 32; k4++) {
            float4 av0 = a_sh4[(k4 * 4 + 0) * 32 + cg];
            float4 av1 = a_sh4[(k4 * 4 + 1) * 32 + cg];
            float4 av2 = a_sh4[(k4 * 4 + 2) * 32 + cg];
            float4 av3 = a_sh4[(k4 * 4 + 3) * 32 + cg];
#pragma unroll
            for (int r = 0; r < 8; r++) {
                float4 hq = h_sh4[(rg * 8 + r) * 32 + k4];  // warp-uniform
                acc[r][0] = fmaf(hq.x, av0.x, fmaf(hq.y, av1.x,
                            fmaf(hq.z, av2.x, fmaf(hq.w, av3.x, acc[r][0]))));
                acc[r][1] = fmaf(hq.x, av0.y, fmaf(hq.y, av1.y,
                            fmaf(hq.z, av2.y, fmaf(hq.w, av3.y, acc[r][1]))));
                acc[r][2] = fmaf(hq.x, av0.z, fmaf(hq.y, av1.z,
                            fmaf(hq.z, av2.z, fmaf(hq.w, av3.z, acc[r][2]))));
                acc[r][3] = fmaf(hq.x, av0.w, fmaf(hq.y, av1.w,
                            fmaf(hq.z, av2.w, fmaf(hq.w, av3.w, acc[r][3]))));
            }
        }

        float4* p4 = (float4*)g_proj;
#pragma unroll
        for (int r = 0; r < 8; r++) {
            int row = rowBase + rg * 8 + r;
            p4[row * 32 + cg] =
                make_float4(acc[r][0], acc[r][1], acc[r][2], acc[r][3]);
        }
    } else {
        int t = (blockIdx.x - PROJ_BLOCKS) * 256 + tid;
        int base = t * 4;
        if (base >= n) return;
        int4 v = ((const int4*)seg)[t];
        int prev = (base == 0) ? -1 : __ldg(&seg[base - 1]);

        int ids[4] = {v.x, v.y, v.z, v.w};
#pragma unroll
        for (int k = 0; k < 4; k++) {
            int s = ids[k];
            for (int g = prev + 1; g <= s; ++g) g_offsets[g] = base + k;
            prev = s;
        }
        if (base + 4 >= n) {
            for (int g = prev + 1; g <= m; ++g) g_offsets[g] = n;
        }
    }
}

// ---------------------------------------------------------------------------
// Flash helpers
// ---------------------------------------------------------------------------
__device__ __forceinline__ float warp_dot(float4 v, float4 p) {
    float d = fmaf(v.x, p.x, fmaf(v.y, p.y, fmaf(v.z, p.z, v.w * p.w)));
    d += __shfl_xor_sync(0xffffffffu, d, 16);
    d += __shfl_xor_sync(0xffffffffu, d, 8);
    d += __shfl_xor_sync(0xffffffffu, d, 4);
    d += __shfl_xor_sync(0xffffffffu, d, 2);
    d += __shfl_xor_sync(0xffffffffu, d, 1);
    return d;
}

// Process one FULL 8-node chunk from smem (bs = chunk base, float4 units).
// Score: 4 lanes per node (lane l -> node l&7, column block l>>3), rotated
// conflict-free smem reads, 2-shfl reduce. Tile max + Sigma-e via 3-step
// butterflies over the node dimension. Accumulate: per-lane columns
// (broadcast rows, conflict-free), so acc layout matches the combine code.
__device__ __forceinline__ void flash8(const float4* __restrict__ bs, int lane,
                                       const float4* __restrict__ preg,
                                       float& m_w, float& z_w, float4& acc) {
    int j   = lane & 7;
    const float4* xrow = bs + j * 32 + (lane >> 3) * 8;

    float s0 = 0.f, s1 = 0.f;
#pragma unroll
    for (int i = 0; i < 8; i += 2) {
        float4 xa = xrow[(i + j) & 7];
        float4 xb = xrow[(i + 1 + j) & 7];
        float4 pa = preg[i];
        float4 pb = preg[i + 1];
        s0 = fmaf(xa.x, pa.x, fmaf(xa.y, pa.y, fmaf(xa.z, pa.z, fmaf(xa.w, pa.w, s0))));
        s1 = fmaf(xb.x, pb.x, fmaf(xb.y, pb.y, fmaf(xb.z, pb.z, fmaf(xb.w, pb.w, s1))));
    }
    float d = s0 + s1;
    d += __shfl_xor_sync(0xffffffffu, d, 8);
    d += __shfl_xor_sync(0xffffffffu, d, 16);   // full dot of node j, all lanes

    // tile max over the 8 nodes (replicated across block-groups)
    float t = d;
    t = fmaxf(t, __shfl_xor_sync(0xffffffffu, t, 1));
    t = fmaxf(t, __shfl_xor_sync(0xffffffffu, t, 2));
    t = fmaxf(t, __shfl_xor_sync(0xffffffffu, t, 4));

    float m_new = fmaxf(m_w, t);
    float c = __expf(m_w - m_new);      // 0 on first chunk (m_w = -inf)
    float e = __expf(d - m_new);        // e_j in lane (j = lane&7)

    // Sigma-e over 8 nodes -> replicated in all lanes (keeps z semantics)
    float es = e;
    es += __shfl_xor_sync(0xffffffffu, es, 1);
    es += __shfl_xor_sync(0xffffffffu, es, 2);
    es += __shfl_xor_sync(0xffffffffu, es, 4);
    z_w = fmaf(z_w, c, es);

    acc.x *= c; acc.y *= c; acc.z *= c; acc.w *= c;
#pragma unroll
    for (int jj = 0; jj < 8; jj++) {
        float  ej = __shfl_sync(0xffffffffu, e, jj);   // lane jj holds e_jj
        float4 v  = bs[jj * 32 + lane];
        acc.x = fmaf(ej, v.x, acc.x);
        acc.y = fmaf(ej, v.y, acc.y);
        acc.z = fmaf(ej, v.z, acc.z);
        acc.w = fmaf(ej, v.w, acc.w);
    }
    m_w = m_new;
}

__device__ __forceinline__ void flash1(float4 v, float4 p,
                                       float& m_w, float& z_w, float4& acc) {
    float d  = warp_dot(v, p);
    float m_new = fmaxf(m_w, d);
    float c = __expf(m_w - m_new);
    float e = __expf(d - m_new);
    z_w   = fmaf(z_w, c, e);
    acc.x = fmaf(acc.x, c, e * v.x);
    acc.y = fmaf(acc.y, c, e * v.y);
    acc.z = fmaf(acc.z, c, e * v.z);
    acc.w = fmaf(acc.w, c, e * v.w);
    m_w = m_new;
}

// ---------------------------------------------------------------------------
// Kernel B: TWO WARPS PER GRAPH, bulk-async pipelined online softmax.
// R12 structure; chunk body replaced by flash8 (amortized reductions).
// ---------------------------------------------------------------------------
__global__ __launch_bounds__(128) void attn_kernel(const float* __restrict__ x,
                                                   float* __restrict__ out,
                                                   int m) {
    __shared__ float4   s_buf[4][STAGES][CHUNK * 32];  // 32 KB
    __shared__ uint64_t s_bar[4][STAGES];
    __shared__ float    s_m[4];
    __shared__ float    s_z[4];
    __shared__ float4   s_accs[2][32];

    int tid  = threadIdx.x;
    int lane = tid & 31;
    int w    = tid >> 5;    // 0..3
    int pp   = w >> 1;      // pair 0..1
    int half = w & 1;
    int g    = blockIdx.x * 2 + pp;

    if (lane == 0) {
        mbar_init(smem_u32(&s_bar[w][0]), 1);
        mbar_init(smem_u32(&s_bar[w][1]), 1);
    }
    __syncthreads();

    bool active = (g < m);
    int s0 = 0, e0 = 0;
    if (active) { s0 = g_offsets[g]; e0 = g_offsets[g + 1]; }
    int cnt = e0 - s0;
    int h0  = (cnt + 1) >> 1;
    int beg = half ? (s0 + h0) : s0;
    int fin = half ? e0 : (s0 + h0);
    int len = fin - beg;
    int nfull = len >> 3;            // full CHUNK-node chunks

    const float4* x4  = (const float4*)x;
    const float4* pr4 = (const float4*)g_proj;

    // proj row in two layouts: pold (lane -> cols 4l..4l+3, for flash1/output)
    // and preg[8] (rotated block layout for flash8 score pass)
    float4 pold = make_float4(0.f, 0.f, 0.f, 0.f);
    float4 preg[8];
#pragma unroll
    for (int i = 0; i < 8; i++) preg[i] = make_float4(0.f, 0.f, 0.f, 0.f);
    if (active && cnt > 0) {
        pold = pr4[g * 32 + lane];
        int j = lane & 7, blk = lane >> 3;
#pragma unroll
        for (int i = 0; i < 8; i++)
            preg[i] = pr4[g * 32 + blk * 8 + ((i + j) & 7)];
    }

    // ---- prologue: fill the pipeline ----
    if (lane == 0) {
        int npre = nfull < STAGES ? nfull : STAGES;
        for (int k = 0; k < npre; k++) {
            uint32_t bar = smem_u32(&s_bar[w][k]);
            mbar_expect(bar, CHUNK * 512u);
            bulk_ld(smem_u32(&s_buf[w][k][0]),
                    x4 + (size_t)(beg + k * CHUNK) * 32, CHUNK * 512u, bar);
        }
    }

    const float NEG_INF = -3.402823466e38f;
    float  m_w = NEG_INF;
    float  z_w = 0.f;
    float4 acc = make_float4(0.f, 0.f, 0.f, 0.f);

    // ---- main pipelined loop ----
    for (int c = 0; c < nfull; c++) {
        int st = c & 1;
        mbar_wait(smem_u32(&s_bar[w][st]), (c >> 1) & 1);
        flash8(&s_buf[w][st][0], lane, preg, m_w, z_w, acc);
        if (c + 2 < nfull && lane == 0) {
            uint32_t bar = smem_u32(&s_bar[w][st]);
            mbar_expect(bar, CHUNK * 512u);
            bulk_ld(smem_u32(&s_buf[w][st][0]),
                    x4 + (size_t)(beg + (c + 2) * CHUNK) * 32, CHUNK * 512u, bar);
        }
    }

    // ---- remainder nodes (<CHUNK) via direct LDG ----
    for (int i = beg + nfull * CHUNK; i < fin; ++i)
        flash1(x4[(size_t)i * 32 + lane], pold, m_w, z_w, acc);

    // ---- pair combine ----
    if (lane == 0) { s_m[w] = m_w; s_z[w] = z_w; }
    if (half) s_accs[pp][lane] = acc;
    __syncthreads();

    if (!half && active) {
        float4* out4 = (float4*)out;
        if (cnt <= 0) {
            out4[g * 32 + lane] = make_float4(0.f, 0.f, 0.f, 0.f);
        } else {
            float  m1 = s_m[w + 1];
            float  z1 = s_z[w + 1];
            float4 a1 = s_accs[pp][lane];
            float mg = fmaxf(m_w, m1);       // finite: half0 non-empty
            float f0 = __expf(m_w - mg);
            float f1 = __expf(m1 - mg);      // 0 if half1 empty
            float z  = fmaf(z_w, f0, z1 * f1);
            float inv = 1.f / z;
            out4[g * 32 + lane] = make_float4(
                fmaf(acc.x, f0, a1.x * f1) * inv,
                fmaf(acc.y, f0, a1.y * f1) * inv,
                fmaf(acc.z, f0, a1.z * f1) * inv,
                fmaf(acc.w, f0, a1.w * f1) * inv);
        }
    }
}

// ---------------------------------------------------------------------------
// Launch: inputs per metadata order: h (M*128 f32), x (N*128 f32),
// a (128*128 f32), segment_ids (N int32). Output: M*128 f32.
// ---------------------------------------------------------------------------
extern "C" void kernel_launch(void* const* d_in, const int* in_sizes, int n_in,
                              void* d_out, int out_size) {
    const float* h   = (const float*)d_in[0];
    const float* x   = (const float*)d_in[1];
    const float* a   = (const float*)d_in[2];
    const int*   seg = (const int*)d_in[3];
    float* out = (float*)d_out;

    int m = in_sizes[0] / D;   // 4096
    int n = in_sizes[3];       // 262144

    int pre_smem = 65536 + 32768;   // a (64KB) + h tile (32KB)
    static bool attr_set = false;
    if (!attr_set) {
        cudaFuncSetAttribute(pre_kernel,
                             cudaFuncAttributeMaxDynamicSharedMemorySize,
                             pre_smem);
        attr_set = true;
    }

    int n4 = (n + 3) / 4;
    int off_blocks = (n4 + 255) / 256;
    pre_kernel<<<PROJ_BLOCKS + off_blocks, 256, pre_smem>>>(h, a, seg, n, m);
    attn_kernel<<<(m + 1) / 2, 128>>>(x, out, m);
}

// round 15
// speedup vs baseline: 1.1987x; 1.0468x over previous
#include <cuda_runtime.h>
#include <cstdint>

#define D 128            // DH == DX == 128
#define MAX_M 4096
#define MAX_N 262144

#define PROJ_BLOCKS 128      // 32 rows each -> 4096 rows
#define OFF_BLOCKS  128      // grid-stride offsets blocks
#define CHUNK  8             // nodes per bulk copy (8 * 512B = 4KB)
#define STAGES 2

// Scratch (no allocations allowed): proj matrix + segment offsets
__device__ float g_proj[MAX_M * D];
__device__ int   g_offsets[MAX_M + 1];

// ---------------------------------------------------------------------------
// PTX helpers: mbarrier + cp.async.bulk
// ---------------------------------------------------------------------------
__device__ __forceinline__ uint32_t smem_u32(const void* p) {
    return (uint32_t)__cvta_generic_to_shared(p);
}
__device__ __forceinline__ void mbar_init(uint32_t bar, uint32_t cnt) {
    asm volatile("mbarrier.init.shared.b64 [%0], %1;" :: "r"(bar), "r"(cnt) : "memory");
}
__device__ __forceinline__ void mbar_expect(uint32_t bar, uint32_t bytes) {
    asm volatile("mbarrier.arrive.expect_tx.shared.b64 _, [%0], %1;"
                 :: "r"(bar), "r"(bytes) : "memory");
}
__device__ __forceinline__ void bulk_ld(uint32_t dst, const void* src,
                                        uint32_t bytes, uint32_t bar) {
    asm volatile(
        "cp.async.bulk.shared::cta.global.mbarrier::complete_tx::bytes [%0], [%1], %2, [%3];"
        :: "r"(dst), "l"(src), "r"(bytes), "r"(bar) : "memory");
}
__device__ __forceinline__ void mbar_wait(uint32_t bar, uint32_t phase) {
    uint32_t done;
    asm volatile(
        "{\n\t.reg .pred p;\n\t"
        "mbarrier.try_wait.parity.acquire.cta.shared::cta.b64 p, [%1], %2;\n\t"
        "selp.b32 %0, 1, 0, p;\n\t}"
        : "=r"(done) : "r"(bar), "r"(phase) : "memory");
    if (!done) {
        asm volatile(
            "{\n\t.reg .pred P1;\n\t"
            "WAIT_LOOP_%=:\n\t"
            "mbarrier.try_wait.parity.acquire.cta.shared::cta.b64 P1, [%0], %1, 0x989680;\n\t"
            "@P1 bra.uni WAIT_DONE_%=;\n\t"
            "bra.uni WAIT_LOOP_%=;\n\t"
            "WAIT_DONE_%=:\n\t}"
            :: "r"(bar), "r"(phase) : "memory");
    }
}

// ---------------------------------------------------------------------------
// Kernel A (fused): blocks [0, PROJ_BLOCKS): proj = h @ a, fat-register
// design at the FFMA/crossbar balance point: 128 blocks x 32 rows.
// Warp rg owns rows rg*4..rg*4+3; lane cg owns cols cg*4..cg*4+3 (4x4 tile).
// `a` staged ONCE (64KB) + h tile (16KB); no __syncthreads in the loop.
// Per-thread FFMA = 2048 (2x less than R12) -> ~2.3us on 128 SMs;
// crossbar 512KB/block overlaps. Blocks [PROJ_BLOCKS, ...): grid-stride
// segment offsets (128 blocks -> whole pre grid is one wave).
// ---------------------------------------------------------------------------
__global__ __launch_bounds__(256) void pre_kernel(const float* __restrict__ h,
                                                  const float* __restrict__ a,
                                                  const int* __restrict__ seg,
                                                  int n, int m) {
    extern __shared__ unsigned char dyn[];
    int tid = threadIdx.x;

    if (blockIdx.x < PROJ_BLOCKS) {
        float4* a_sh4 = (float4*)dyn;              // 64 KB: all of a
        float4* h_sh4 = (float4*)(dyn + 65536);    // 16 KB: 32 h rows

        int cg = tid & 31;    // cols cg*4..cg*4+3
        int rg = tid >> 5;    // rows rg*4..rg*4+3
        int rowBase = blockIdx.x * 32;

        const float4* h4 = (const float4*)h;
        const float4* a4 = (const float4*)a;

#pragma unroll
        for (int i = 0; i < 16; i++)
            a_sh4[tid + i * 256] = a4[tid + i * 256];
#pragma unroll
        for (int i = 0; i < 4; i++)
            h_sh4[tid + i * 256] = h4[rowBase * 32 + tid + i * 256];
        __syncthreads();

        float acc[4][4];
#pragma unroll
        for (int r = 0; r < 4; r++)
#pragma unroll
            for (int c = 0; c < 4; c++) acc[r][c] = 0.f;

#pragma unroll 4
        for (int k4 = 0; k4 < 32; k4++) {
            float4 av0 = a_sh4[(k4 * 4 + 0) * 32 + cg];
            float4 av1 = a_sh4[(k4 * 4 + 1) * 32 + cg];
            float4 av2 = a_sh4[(k4 * 4 + 2) * 32 + cg];
            float4 av3 = a_sh4[(k4 * 4 + 3) * 32 + cg];
#pragma unroll
            for (int r = 0; r < 4; r++) {
                float4 hq = h_sh4[(rg * 4 + r) * 32 + k4];  // warp-uniform
                acc[r][0] = fmaf(hq.x, av0.x, fmaf(hq.y, av1.x,
                            fmaf(hq.z, av2.x, fmaf(hq.w, av3.x, acc[r][0]))));
                acc[r][1] = fmaf(hq.x, av0.y, fmaf(hq.y, av1.y,
                            fmaf(hq.z, av2.y, fmaf(hq.w, av3.y, acc[r][1]))));
                acc[r][2] = fmaf(hq.x, av0.z, fmaf(hq.y, av1.z,
                            fmaf(hq.z, av2.z, fmaf(hq.w, av3.z, acc[r][2]))));
                acc[r][3] = fmaf(hq.x, av0.w, fmaf(hq.y, av1.w,
                            fmaf(hq.z, av2.w, fmaf(hq.w, av3.w, acc[r][3]))));
            }
        }

        float4* p4 = (float4*)g_proj;
#pragma unroll
        for (int r = 0; r < 4; r++) {
            int row = rowBase + rg * 4 + r;
            p4[row * 32 + cg] =
                make_float4(acc[r][0], acc[r][1], acc[r][2], acc[r][3]);
        }
    } else {
        // ------------- segment offsets (grid-stride, int4 per thread) -------
        int nt4 = (n + 3) >> 2;
        for (int t = (blockIdx.x - PROJ_BLOCKS) * 256 + tid; t < nt4;
             t += OFF_BLOCKS * 256) {
            int base = t * 4;
            int4 v = ((const int4*)seg)[t];
            int prev = (base == 0) ? -1 : __ldg(&seg[base - 1]);

            int ids[4] = {v.x, v.y, v.z, v.w};
#pragma unroll
            for (int k = 0; k < 4; k++) {
                int s = ids[k];
                for (int g = prev + 1; g <= s; ++g) g_offsets[g] = base + k;
                prev = s;
            }
            if (base + 4 >= n) {
                for (int g = prev + 1; g <= m; ++g) g_offsets[g] = n;
            }
        }
    }
}

// ---------------------------------------------------------------------------
// Flash helpers (R12 versions — best measured)
// ---------------------------------------------------------------------------
__device__ __forceinline__ float warp_dot(float4 v, float4 p) {
    float d = fmaf(v.x, p.x, fmaf(v.y, p.y, fmaf(v.z, p.z, v.w * p.w)));
    d += __shfl_xor_sync(0xffffffffu, d, 16);
    d += __shfl_xor_sync(0xffffffffu, d, 8);
    d += __shfl_xor_sync(0xffffffffu, d, 4);
    d += __shfl_xor_sync(0xffffffffu, d, 2);
    d += __shfl_xor_sync(0xffffffffu, d, 1);
    return d;
}

__device__ __forceinline__ void flash4(const float4* __restrict__ b, float4 p,
                                       float& m_w, float& z_w, float4& acc) {
    float4 v0 = b[0];
    float4 v1 = b[32];
    float4 v2 = b[64];
    float4 v3 = b[96];
    float d0 = warp_dot(v0, p);
    float d1 = warp_dot(v1, p);
    float d2 = warp_dot(v2, p);
    float d3 = warp_dot(v3, p);
    float m_new = fmaxf(fmaxf(m_w, fmaxf(d0, d1)), fmaxf(d2, d3));
    float c  = __expf(m_w - m_new);
    float e0 = __expf(d0 - m_new);
    float e1 = __expf(d1 - m_new);
    float e2 = __expf(d2 - m_new);
    float e3 = __expf(d3 - m_new);
    z_w   = fmaf(z_w, c, (e0 + e1) + (e2 + e3));
    acc.x = fmaf(acc.x, c, fmaf(e0, v0.x, fmaf(e1, v1.x, fmaf(e2, v2.x, e3 * v3.x))));
    acc.y = fmaf(acc.y, c, fmaf(e0, v0.y, fmaf(e1, v1.y, fmaf(e2, v2.y, e3 * v3.y))));
    acc.z = fmaf(acc.z, c, fmaf(e0, v0.z, fmaf(e1, v1.z, fmaf(e2, v2.z, e3 * v3.z))));
    acc.w = fmaf(acc.w, c, fmaf(e0, v0.w, fmaf(e1, v1.w, fmaf(e2, v2.w, e3 * v3.w))));
    m_w = m_new;
}

__device__ __forceinline__ void flash1(float4 v, float4 p,
                                       float& m_w, float& z_w, float4& acc) {
    float d  = warp_dot(v, p);
    float m_new = fmaxf(m_w, d);
    float c = __expf(m_w - m_new);
    float e = __expf(d - m_new);
    z_w   = fmaf(z_w, c, e);
    acc.x = fmaf(acc.x, c, e * v.x);
    acc.y = fmaf(acc.y, c, e * v.y);
    acc.z = fmaf(acc.z, c, e * v.z);
    acc.w = fmaf(acc.w, c, e * v.w);
    m_w = m_new;
}

// ---------------------------------------------------------------------------
// Kernel B: TWO WARPS PER GRAPH, bulk-async pipelined online softmax.
// (R12 version verbatim — best measured attn.)
// ---------------------------------------------------------------------------
__global__ __launch_bounds__(128) void attn_kernel(const float* __restrict__ x,
                                                   float* __restrict__ out,
                                                   int m) {
    __shared__ float4   s_buf[4][STAGES][CHUNK * 32];  // 32 KB
    __shared__ uint64_t s_bar[4][STAGES];
    __shared__ float    s_m[4];
    __shared__ float    s_z[4];
    __shared__ float4   s_accs[2][32];

    int tid  = threadIdx.x;
    int lane = tid & 31;
    int w    = tid >> 5;    // 0..3
    int pp   = w >> 1;      // pair 0..1
    int half = w & 1;
    int g    = blockIdx.x * 2 + pp;

    if (lane == 0) {
        mbar_init(smem_u32(&s_bar[w][0]), 1);
        mbar_init(smem_u32(&s_bar[w][1]), 1);
    }
    __syncthreads();

    bool active = (g < m);
    int s0 = 0, e0 = 0;
    if (active) { s0 = g_offsets[g]; e0 = g_offsets[g + 1]; }
    int cnt = e0 - s0;
    int h0  = (cnt + 1) >> 1;
    int beg = half ? (s0 + h0) : s0;
    int fin = half ? e0 : (s0 + h0);
    int len = fin - beg;
    int nfull = len >> 3;            // full CHUNK-node chunks

    const float4* x4 = (const float4*)x;

    float4 p = make_float4(0.f, 0.f, 0.f, 0.f);
    if (active && cnt > 0)
        p = ((const float4*)g_proj)[g * 32 + lane];

    // ---- prologue: fill the pipeline ----
    if (lane == 0) {
        int npre = nfull < STAGES ? nfull : STAGES;
        for (int k = 0; k < npre; k++) {
            uint32_t bar = smem_u32(&s_bar[w][k]);
            mbar_expect(bar, CHUNK * 512u);
            bulk_ld(smem_u32(&s_buf[w][k][0]),
                    x4 + (size_t)(beg + k * CHUNK) * 32, CHUNK * 512u, bar);
        }
    }

    const float NEG_INF = -3.402823466e38f;
    float  m_w = NEG_INF;
    float  z_w = 0.f;
    float4 acc = make_float4(0.f, 0.f, 0.f, 0.f);

    // ---- main pipelined loop ----
    for (int c = 0; c < nfull; c++) {
        int st = c & 1;
        mbar_wait(smem_u32(&s_bar[w][st]), (c >> 1) & 1);
        const float4* b = &s_buf[w][st][lane];
        flash4(b,       p, m_w, z_w, acc);   // nodes 0..3
        flash4(b + 128, p, m_w, z_w, acc);   // nodes 4..7
        if (c + 2 < nfull && lane == 0) {
            uint32_t bar = smem_u32(&s_bar[w][st]);
            mbar_expect(bar, CHUNK * 512u);
            bulk_ld(smem_u32(&s_buf[w][st][0]),
                    x4 + (size_t)(beg + (c + 2) * CHUNK) * 32, CHUNK * 512u, bar);
        }
    }

    // ---- remainder nodes (<CHUNK) via direct LDG ----
    for (int i = beg + nfull * CHUNK; i < fin; ++i)
        flash1(x4[(size_t)i * 32 + lane], p, m_w, z_w, acc);

    // ---- pair combine ----
    if (lane == 0) { s_m[w] = m_w; s_z[w] = z_w; }
    if (half) s_accs[pp][lane] = acc;
    __syncthreads();

    if (!half && active) {
        float4* out4 = (float4*)out;
        if (cnt <= 0) {
            out4[g * 32 + lane] = make_float4(0.f, 0.f, 0.f, 0.f);
        } else {
            float  m1 = s_m[w + 1];
            float  z1 = s_z[w + 1];
            float4 a1 = s_accs[pp][lane];
            float mg = fmaxf(m_w, m1);       // finite: half0 non-empty
            float f0 = __expf(m_w - mg);
            float f1 = __expf(m1 - mg);      // 0 if half1 empty
            float z  = fmaf(z_w, f0, z1 * f1);
            float inv = 1.f / z;
            out4[g * 32 + lane] = make_float4(
                fmaf(acc.x, f0, a1.x * f1) * inv,
                fmaf(acc.y, f0, a1.y * f1) * inv,
                fmaf(acc.z, f0, a1.z * f1) * inv,
                fmaf(acc.w, f0, a1.w * f1) * inv);
        }
    }
}

// ---------------------------------------------------------------------------
// Launch: inputs per metadata order: h (M*128 f32), x (N*128 f32),
// a (128*128 f32), segment_ids (N int32). Output: M*128 f32.
// ---------------------------------------------------------------------------
extern "C" void kernel_launch(void* const* d_in, const int* in_sizes, int n_in,
                              void* d_out, int out_size) {
    const float* h   = (const float*)d_in[0];
    const float* x   = (const float*)d_in[1];
    const float* a   = (const float*)d_in[2];
    const int*   seg = (const int*)d_in[3];
    float* out = (float*)d_out;

    int m = in_sizes[0] / D;   // 4096
    int n = in_sizes[3];       // 262144

    int pre_smem = 65536 + 16384;   // a (64KB) + h tile (16KB)
    static bool attr_set = false;
    if (!attr_set) {
        cudaFuncSetAttribute(pre_kernel,
                             cudaFuncAttributeMaxDynamicSharedMemorySize,
                             pre_smem);
        attr_set = true;
    }

    pre_kernel<<<PROJ_BLOCKS + OFF_BLOCKS, 256, pre_smem>>>(h, a, seg, n, m);
    attn_kernel<<<(m + 1) / 2, 128>>>(x, out, m);
}

// round 16
// speedup vs baseline: 1.2184x; 1.0164x over previous
#include <cuda_runtime.h>
#include <cstdint>

#define D 128            // DH == DX == 128
#define MAX_M 4096
#define MAX_N 262144

#define PROJ_BLOCKS 128      // 32 rows each -> 4096 rows
#define OFF_BLOCKS  128      // grid-stride offsets blocks
#define CHUNK  8             // nodes per bulk copy (8 * 512B = 4KB)
#define STAGES 2

// Scratch (no allocations allowed): proj matrix + segment offsets
__device__ float g_proj[MAX_M * D];
__device__ int   g_offsets[MAX_M + 1];

// ---------------------------------------------------------------------------
// PTX helpers: mbarrier + cp.async.bulk + f32x2
// ---------------------------------------------------------------------------
__device__ __forceinline__ uint32_t smem_u32(const void* p) {
    return (uint32_t)__cvta_generic_to_shared(p);
}
__device__ __forceinline__ void mbar_init(uint32_t bar, uint32_t cnt) {
    asm volatile("mbarrier.init.shared.b64 [%0], %1;" :: "r"(bar), "r"(cnt) : "memory");
}
__device__ __forceinline__ void mbar_expect(uint32_t bar, uint32_t bytes) {
    asm volatile("mbarrier.arrive.expect_tx.shared.b64 _, [%0], %1;"
                 :: "r"(bar), "r"(bytes) : "memory");
}
__device__ __forceinline__ void bulk_ld(uint32_t dst, const void* src,
                                        uint32_t bytes, uint32_t bar) {
    asm volatile(
        "cp.async.bulk.shared::cta.global.mbarrier::complete_tx::bytes [%0], [%1], %2, [%3];"
        :: "r"(dst), "l"(src), "r"(bytes), "r"(bar) : "memory");
}
__device__ __forceinline__ void mbar_wait(uint32_t bar, uint32_t phase) {
    uint32_t done;
    asm volatile(
        "{\n\t.reg .pred p;\n\t"
        "mbarrier.try_wait.parity.acquire.cta.shared::cta.b64 p, [%1], %2;\n\t"
        "selp.b32 %0, 1, 0, p;\n\t}"
        : "=r"(done) : "r"(bar), "r"(phase) : "memory");
    if (!done) {
        asm volatile(
            "{\n\t.reg .pred P1;\n\t"
            "WAIT_LOOP_%=:\n\t"
            "mbarrier.try_wait.parity.acquire.cta.shared::cta.b64 P1, [%0], %1, 0x989680;\n\t"
            "@P1 bra.uni WAIT_DONE_%=;\n\t"
            "bra.uni WAIT_LOOP_%=;\n\t"
            "WAIT_DONE_%=:\n\t}"
            :: "r"(bar), "r"(phase) : "memory");
    }
}
__device__ __forceinline__ unsigned long long pack2(float lo, float hi) {
    unsigned long long r;
    asm("mov.b64 %0, {%1, %2};" : "=l"(r) : "f"(lo), "f"(hi));
    return r;
}
__device__ __forceinline__ void fma2(unsigned long long& d,
                                     unsigned long long a,
                                     unsigned long long b) {
    asm("fma.rn.f32x2 %0, %1, %2, %0;" : "+l"(d) : "l"(a), "l"(b));
}

// ---------------------------------------------------------------------------
// Kernel A (fused): blocks [0, PROJ_BLOCKS): proj = h @ a with PACKED f32x2
// FFMA (halves fma-pipe instruction count vs scalar; `a` column-pairs come
// free via ulonglong2 smem loads; h broadcast dup on the alu pipe overlaps).
// Blocks [PROJ_BLOCKS, ...): grid-stride segment offsets.
// Calls cudaTriggerProgrammaticLaunchCompletion() at entry so the dependent
// attn kernel's launch setup overlaps this kernel's body (PDL).
// ---------------------------------------------------------------------------
__global__ __launch_bounds__(256) void pre_kernel(const float* __restrict__ h,
                                                  const float* __restrict__ a,
                                                  const int* __restrict__ seg,
                                                  int n, int m) {
    cudaTriggerProgrammaticLaunchCompletion();
    extern __shared__ unsigned char dyn[];
    int tid = threadIdx.x;

    if (blockIdx.x < PROJ_BLOCKS) {
        float4* a_sh4 = (float4*)dyn;              // 64 KB: all of a
        float4* h_sh4 = (float4*)(dyn + 65536);    // 16 KB: 32 h rows
        const ulonglong2* a_shp = (const ulonglong2*)dyn;  // aliased pair view

        int cg = tid & 31;    // cols cg*4..cg*4+3
        int rg = tid >> 5;    // rows rg*4..rg*4+3
        int rowBase = blockIdx.x * 32;

        const float4* h4 = (const float4*)h;
        const float4* a4 = (const float4*)a;

#pragma unroll
        for (int i = 0; i < 16; i++)
            a_sh4[tid + i * 256] = a4[tid + i * 256];
#pragma unroll
        for (int i = 0; i < 4; i++)
            h_sh4[tid + i * 256] = h4[rowBase * 32 + tid + i * 256];
        __syncthreads();

        unsigned long long acc01[4], acc23[4];
#pragma unroll
        for (int r = 0; r < 4; r++) { acc01[r] = 0ull; acc23[r] = 0ull; }

#pragma unroll 4
        for (int k4 = 0; k4 < 32; k4++) {
            // a rows k=4k4..4k4+3, cols cg*4..cg*4+3 as packed pairs
            ulonglong2 av0 = a_shp[(k4 * 4 + 0) * 32 + cg];
            ulonglong2 av1 = a_shp[(k4 * 4 + 1) * 32 + cg];
            ulonglong2 av2 = a_shp[(k4 * 4 + 2) * 32 + cg];
            ulonglong2 av3 = a_shp[(k4 * 4 + 3) * 32 + cg];
#pragma unroll
            for (int r = 0; r < 4; r++) {
                float4 hq = h_sh4[(rg * 4 + r) * 32 + k4];  // warp-uniform
                unsigned long long h0 = pack2(hq.x, hq.x);
                unsigned long long h1 = pack2(hq.y, hq.y);
                unsigned long long h2 = pack2(hq.z, hq.z);
                unsigned long long h3 = pack2(hq.w, hq.w);
                fma2(acc01[r], h0, av0.x); fma2(acc23[r], h0, av0.y);
                fma2(acc01[r], h1, av1.x); fma2(acc23[r], h1, av1.y);
                fma2(acc01[r], h2, av2.x); fma2(acc23[r], h2, av2.y);
                fma2(acc01[r], h3, av3.x); fma2(acc23[r], h3, av3.y);
            }
        }

        ulonglong2* p2 = (ulonglong2*)g_proj;
#pragma unroll
        for (int r = 0; r < 4; r++) {
            int row = rowBase + rg * 4 + r;
            p2[row * 32 + cg] = make_ulonglong2(acc01[r], acc23[r]);
        }
    } else {
        // ------------- segment offsets (grid-stride, int4 per thread) -------
        int nt4 = (n + 3) >> 2;
        for (int t = (blockIdx.x - PROJ_BLOCKS) * 256 + tid; t < nt4;
             t += OFF_BLOCKS * 256) {
            int base = t * 4;
            int4 v = ((const int4*)seg)[t];
            int prev = (base == 0) ? -1 : __ldg(&seg[base - 1]);

            int ids[4] = {v.x, v.y, v.z, v.w};
#pragma unroll
            for (int k = 0; k < 4; k++) {
                int s = ids[k];
                for (int g = prev + 1; g <= s; ++g) g_offsets[g] = base + k;
                prev = s;
            }
            if (base + 4 >= n) {
                for (int g = prev + 1; g <= m; ++g) g_offsets[g] = n;
            }
        }
    }
}

// ---------------------------------------------------------------------------
// Flash helpers (R12 versions — best measured)
// ---------------------------------------------------------------------------
__device__ __forceinline__ float warp_dot(float4 v, float4 p) {
    float d = fmaf(v.x, p.x, fmaf(v.y, p.y, fmaf(v.z, p.z, v.w * p.w)));
    d += __shfl_xor_sync(0xffffffffu, d, 16);
    d += __shfl_xor_sync(0xffffffffu, d, 8);
    d += __shfl_xor_sync(0xffffffffu, d, 4);
    d += __shfl_xor_sync(0xffffffffu, d, 2);
    d += __shfl_xor_sync(0xffffffffu, d, 1);
    return d;
}

__device__ __forceinline__ void flash4(const float4* __restrict__ b, float4 p,
                                       float& m_w, float& z_w, float4& acc) {
    float4 v0 = b[0];
    float4 v1 = b[32];
    float4 v2 = b[64];
    float4 v3 = b[96];
    float d0 = warp_dot(v0, p);
    float d1 = warp_dot(v1, p);
    float d2 = warp_dot(v2, p);
    float d3 = warp_dot(v3, p);
    float m_new = fmaxf(fmaxf(m_w, fmaxf(d0, d1)), fmaxf(d2, d3));
    float c  = __expf(m_w - m_new);
    float e0 = __expf(d0 - m_new);
    float e1 = __expf(d1 - m_new);
    float e2 = __expf(d2 - m_new);
    float e3 = __expf(d3 - m_new);
    z_w   = fmaf(z_w, c, (e0 + e1) + (e2 + e3));
    acc.x = fmaf(acc.x, c, fmaf(e0, v0.x, fmaf(e1, v1.x, fmaf(e2, v2.x, e3 * v3.x))));
    acc.y = fmaf(acc.y, c, fmaf(e0, v0.y, fmaf(e1, v1.y, fmaf(e2, v2.y, e3 * v3.y))));
    acc.z = fmaf(acc.z, c, fmaf(e0, v0.z, fmaf(e1, v1.z, fmaf(e2, v2.z, e3 * v3.z))));
    acc.w = fmaf(acc.w, c, fmaf(e0, v0.w, fmaf(e1, v1.w, fmaf(e2, v2.w, e3 * v3.w))));
    m_w = m_new;
}

__device__ __forceinline__ void flash1(float4 v, float4 p,
                                       float& m_w, float& z_w, float4& acc) {
    float d  = warp_dot(v, p);
    float m_new = fmaxf(m_w, d);
    float c = __expf(m_w - m_new);
    float e = __expf(d - m_new);
    z_w   = fmaf(z_w, c, e);
    acc.x = fmaf(acc.x, c, e * v.x);
    acc.y = fmaf(acc.y, c, e * v.y);
    acc.z = fmaf(acc.z, c, e * v.z);
    acc.w = fmaf(acc.w, c, e * v.w);
    m_w = m_new;
}

// ---------------------------------------------------------------------------
// Kernel B: TWO WARPS PER GRAPH, bulk-async pipelined online softmax.
// (R12 version; adds cudaGridDependencySynchronize() before dependent reads
// so it can be launched with PDL overlap.)
// ---------------------------------------------------------------------------
__global__ __launch_bounds__(128) void attn_kernel(const float* __restrict__ x,
                                                   float* __restrict__ out,
                                                   int m) {
    __shared__ float4   s_buf[4][STAGES][CHUNK * 32];  // 32 KB
    __shared__ uint64_t s_bar[4][STAGES];
    __shared__ float    s_m[4];
    __shared__ float    s_z[4];
    __shared__ float4   s_accs[2][32];

    int tid  = threadIdx.x;
    int lane = tid & 31;
    int w    = tid >> 5;    // 0..3
    int pp   = w >> 1;      // pair 0..1
    int half = w & 1;
    int g    = blockIdx.x * 2 + pp;

    if (lane == 0) {
        mbar_init(smem_u32(&s_bar[w][0]), 1);
        mbar_init(smem_u32(&s_bar[w][1]), 1);
    }
    __syncthreads();

    // PDL: wait for pre_kernel's writes (g_offsets, g_proj) to be visible
    cudaGridDependencySynchronize();

    bool active = (g < m);
    int s0 = 0, e0 = 0;
    if (active) { s0 = g_offsets[g]; e0 = g_offsets[g + 1]; }
    int cnt = e0 - s0;
    int h0  = (cnt + 1) >> 1;
    int beg = half ? (s0 + h0) : s0;
    int fin = half ? e0 : (s0 + h0);
    int len = fin - beg;
    int nfull = len >> 3;            // full CHUNK-node chunks

    const float4* x4 = (const float4*)x;

    float4 p = make_float4(0.f, 0.f, 0.f, 0.f);
    if (active && cnt > 0)
        p = ((const float4*)g_proj)[g * 32 + lane];

    // ---- prologue: fill the pipeline ----
    if (lane == 0) {
        int npre = nfull < STAGES ? nfull : STAGES;
        for (int k = 0; k < npre; k++) {
            uint32_t bar = smem_u32(&s_bar[w][k]);
            mbar_expect(bar, CHUNK * 512u);
            bulk_ld(smem_u32(&s_buf[w][k][0]),
                    x4 + (size_t)(beg + k * CHUNK) * 32, CHUNK * 512u, bar);
        }
    }

    const float NEG_INF = -3.402823466e38f;
    float  m_w = NEG_INF;
    float  z_w = 0.f;
    float4 acc = make_float4(0.f, 0.f, 0.f, 0.f);

    // ---- main pipelined loop ----
    for (int c = 0; c < nfull; c++) {
        int st = c & 1;
        mbar_wait(smem_u32(&s_bar[w][st]), (c >> 1) & 1);
        const float4* b = &s_buf[w][st][lane];
        flash4(b,       p, m_w, z_w, acc);   // nodes 0..3
        flash4(b + 128, p, m_w, z_w, acc);   // nodes 4..7
        if (c + 2 < nfull && lane == 0) {
            uint32_t bar = smem_u32(&s_bar[w][st]);
            mbar_expect(bar, CHUNK * 512u);
            bulk_ld(smem_u32(&s_buf[w][st][0]),
                    x4 + (size_t)(beg + (c + 2) * CHUNK) * 32, CHUNK * 512u, bar);
        }
    }

    // ---- remainder nodes (<CHUNK) via direct LDG ----
    for (int i = beg + nfull * CHUNK; i < fin; ++i)
        flash1(x4[(size_t)i * 32 + lane], p, m_w, z_w, acc);

    // ---- pair combine ----
    if (lane == 0) { s_m[w] = m_w; s_z[w] = z_w; }
    if (half) s_accs[pp][lane] = acc;
    __syncthreads();

    if (!half && active) {
        float4* out4 = (float4*)out;
        if (cnt <= 0) {
            out4[g * 32 + lane] = make_float4(0.f, 0.f, 0.f, 0.f);
        } else {
            float  m1 = s_m[w + 1];
            float  z1 = s_z[w + 1];
            float4 a1 = s_accs[pp][lane];
            float mg = fmaxf(m_w, m1);       // finite: half0 non-empty
            float f0 = __expf(m_w - mg);
            float f1 = __expf(m1 - mg);      // 0 if half1 empty
            float z  = fmaf(z_w, f0, z1 * f1);
            float inv = 1.f / z;
            out4[g * 32 + lane] = make_float4(
                fmaf(acc.x, f0, a1.x * f1) * inv,
                fmaf(acc.y, f0, a1.y * f1) * inv,
                fmaf(acc.z, f0, a1.z * f1) * inv,
                fmaf(acc.w, f0, a1.w * f1) * inv);
        }
    }
}

// ---------------------------------------------------------------------------
// Launch: inputs per metadata order: h (M*128 f32), x (N*128 f32),
// a (128*128 f32), segment_ids (N int32). Output: M*128 f32.
// attn launched with Programmatic Stream Serialization (PDL) so its launch
// setup overlaps pre_kernel's execution.
// ---------------------------------------------------------------------------
extern "C" void kernel_launch(void* const* d_in, const int* in_sizes, int n_in,
                              void* d_out, int out_size) {
    const float* h   = (const float*)d_in[0];
    const float* x   = (const float*)d_in[1];
    const float* a   = (const float*)d_in[2];
    const int*   seg = (const int*)d_in[3];
    float* out = (float*)d_out;

    int m = in_sizes[0] / D;   // 4096
    int n = in_sizes[3];       // 262144

    int pre_smem = 65536 + 16384;   // a (64KB) + h tile (16KB)
    static bool attr_set = false;
    if (!attr_set) {
        cudaFuncSetAttribute(pre_kernel,
                             cudaFuncAttributeMaxDynamicSharedMemorySize,
                             pre_smem);
        attr_set = true;
    }

    pre_kernel<<<PROJ_BLOCKS + OFF_BLOCKS, 256, pre_smem>>>(h, a, seg, n, m);

    cudaLaunchConfig_t cfg = {};
    cfg.gridDim  = dim3((unsigned)((m + 1) / 2), 1, 1);
    cfg.blockDim = dim3(128, 1, 1);
    cudaLaunchAttribute attrs[1];
    attrs[0].id = cudaLaunchAttributeProgrammaticStreamSerialization;
    attrs[0].val.programmaticStreamSerializationAllowed = 1;
    cfg.attrs = attrs;
    cfg.numAttrs = 1;
    cudaLaunchKernelEx(&cfg, attn_kernel, x, out, m);
}